// round 17
// baseline (speedup 1.0000x reference)
#include <cuda_runtime.h>
#include <cfloat>

// Symmetric squared-Hausdorff per batch — single persistent kernel, ONE grid
// barrier (R17). d^2(p,g) = |p|^2 + s, s = |g|^2 - 2 p.g.
//
// Grid = 128 blocks x 512 threads (1 block/SM, all co-resident).
// Phase AB (per dir,b,och): load 1024 outer pts (writing the pack chunk
//   (-2p,|p|^2) as a side effect — covers both arrays across all blocks);
//   block-local candidate = radius argmax of those 1024; LB = exact min-d^2
//   of candidate over ALL 4096 raw inner pts (8 evals/thread) minus margin
//   -> g_lb4[dir][b][och]; branchless f32x2 scan of first 128 inner pts;
//   certified (v < own LB) -> block max -> g_bmax4 slot (plain store);
//   uncertified -> dense global list (atomicAdd g_cnt).
// [one grid barrier]
// Phase C: 2048 warps work-steal list entries; threshold = max of the 4
//   margined LBs of (dir,b); half-round [128,256) + vote, then 15 x 256-pt
//   vote rounds over [256,4096); exact values atomicMax'ed into the point's
//   g_bmax4 slot. Done-ticket: last block writes out[16] and resets the
//   shared scalars for the next launch (zero-init covers the first).
//
// Exactness: each LB is a true point's exact min-d^2 (<= answer); certified
// partials lie in [true, LB) and cannot win the max; the argmax never
// certifies and its exact min is computed from identically-evaluated
// per-pair values. All combines are order-independent -> deterministic.

#define BATCH   16
#define NPTS    4096
#define NBLK    128
#define T       512
#define OPT     2
#define PTSBLK  (T * OPT)            // 1024 outer pts per block
#define OCH     4
#define P1PTS   128                  // phase-1 inner points
#define P1SLOTS (P1PTS / 2)          // 64 packed pair-slots
#define TAIL0   256                  // start of evenly-divisible tail region
#define VC      8                    // tail lane-iters per vote round (256 pts)

__device__ float4       g_pack[2][BATCH][NPTS];     // (-2gx,-2gy,-2gz,|g|^2)
__device__ float        g_lb4[2][BATCH][OCH];       // margined per-block LB
__device__ unsigned int g_bmax4[2][BATCH][OCH];     // encoded per-chunk max
__device__ int2         g_list[2 * BATCH * NPTS];   // (code, partial bits)
__device__ int          g_cnt;                      // reset at end of launch
__device__ int          g_ticket;                   // reset at end of launch
__device__ unsigned int g_done;                     // reset at end of launch
__device__ unsigned int g_bar;                      // monotonic generation

typedef unsigned long long u64t;

__device__ __forceinline__ u64t fma2(u64t a, u64t b, u64t c) {
    u64t d;
    asm("fma.rn.f32x2 %0, %1, %2, %3;" : "=l"(d) : "l"(a), "l"(b), "l"(c));
    return d;
}
__device__ __forceinline__ u64t pk(float lo, float hi) {
    u64t d;
    asm("mov.b64 %0, {%1, %2};" : "=l"(d) : "f"(lo), "f"(hi));
    return d;
}
__device__ __forceinline__ float2 upk(u64t v) {
    float2 r;
    asm("mov.b64 {%0, %1}, %2;" : "=f"(r.x), "=f"(r.y) : "l"(v));
    return r;
}
// monotonic float<->uint (total order preserved under unsigned compare)
__device__ __forceinline__ unsigned int encf(float v) {
    unsigned int b = __float_as_uint(v);
    return (b & 0x80000000u) ? ~b : (b | 0x80000000u);
}
__device__ __forceinline__ float decf(unsigned int u) {
    unsigned int b = (u & 0x80000000u) ? (u & 0x7fffffffu) : ~u;
    return __uint_as_float(b);
}
__device__ __forceinline__ unsigned int ldacq(const unsigned int* p) {
    unsigned int v;
    asm volatile("ld.acquire.gpu.u32 %0, [%1];" : "=r"(v) : "l"(p) : "memory");
    return v;
}

// generation-counting grid barrier (monotonic counter, acquire-load poll)
__device__ __forceinline__ void gbar() {
    __threadfence();
    __syncthreads();
    if (threadIdx.x == 0) {
        unsigned int gen = atomicAdd(&g_bar, 1u) / NBLK;
        while (ldacq(&g_bar) / NBLK == gen) { }
    }
    __syncthreads();
}

__global__ void __launch_bounds__(T, 1)
hd_fused(const float* __restrict__ preds, const float* __restrict__ gts,
         float* __restrict__ out) {
    __shared__ __align__(16) ulonglong2 shv[P1SLOTS * 2];   // 2 KB
    __shared__ float  s_red[T / 32];
    __shared__ int    s_redi[T / 32];
    __shared__ float4 s_cand;
    __shared__ float  s_lb;
    __shared__ bool   s_last;

    const int bid = blockIdx.x;
    const int tid = threadIdx.x;
    const int lane = tid & 31;

    const int dir = bid >> 6, b = (bid >> 2) & 15, och = bid & 3;
    const float* __restrict__ outer = (dir == 0 ? preds : gts) + (size_t)b * NPTS * 3;
    const float* __restrict__ inner = (dir == 0 ? gts : preds) + (size_t)b * NPTS * 3;

    // ---- stage first P1SLOTS inner pairs (raw -> packed smem) ----
    if (tid < P1SLOTS) {
        const float* gp = inner + (size_t)tid * 6;
        float x0 = gp[0], y0 = gp[1], z0 = gp[2];
        float x1 = gp[3], y1 = gp[4], z1 = gp[5];
        ((float4*)shv)[tid * 2 + 0] = make_float4(-2.f*x0, -2.f*x1, -2.f*y0, -2.f*y1);
        ((float4*)shv)[tid * 2 + 1] = make_float4(-2.f*z0, -2.f*z1,
                                fmaf(x0, x0, fmaf(y0, y0, z0*z0)),
                                fmaf(x1, x1, fmaf(y1, y1, z1*z1)));
    }

    // ---- load outer pts, write pack chunk (side effect), local argmax ----
    const int gbase = och * PTSBLK;
    float px[OPT], py[OPT], pz[OPT], rq[OPT];
    float bestr = -1.0f; int besti = 0;
#pragma unroll
    for (int o = 0; o < OPT; o++) {
        int i = gbase + o * T + tid;
        px[o] = outer[3*i]; py[o] = outer[3*i+1]; pz[o] = outer[3*i+2];
        rq[o] = fmaf(px[o], px[o], fmaf(py[o], py[o], pz[o]*pz[o]));
        g_pack[dir][b][i] = make_float4(-2.0f*px[o], -2.0f*py[o], -2.0f*pz[o], rq[o]);
        if (rq[o] > bestr || (rq[o] == bestr && i < besti)) { bestr = rq[o]; besti = i; }
    }
#pragma unroll
    for (int off = 16; off; off >>= 1) {
        float r2 = __shfl_xor_sync(0xffffffffu, bestr, off);
        int   i2 = __shfl_xor_sync(0xffffffffu, besti, off);
        if (r2 > bestr || (r2 == bestr && i2 < besti)) { bestr = r2; besti = i2; }
    }
    if (lane == 0) { s_red[tid>>5] = bestr; s_redi[tid>>5] = besti; }
    __syncthreads();
    if (tid == 0) {
        float r = s_red[0]; int i = s_redi[0];
#pragma unroll
        for (int w = 1; w < T/32; w++)
            if (s_red[w] > r || (s_red[w] == r && s_redi[w] < i)) { r = s_red[w]; i = s_redi[w]; }
        s_cand = make_float4(outer[3*i], outer[3*i+1], outer[3*i+2], r);
    }
    __syncthreads();

    // ---- block-local LB: candidate vs ALL 4096 raw inner pts ----
    {
        const float cx = s_cand.x, cy = s_cand.y, cz = s_cand.z;
        float cm = FLT_MAX;
#pragma unroll
        for (int k = 0; k < NPTS / T; k++) {          // 8 evals/thread
            int j = tid + k * T;
            float gx = inner[3*j], gy = inner[3*j+1], gz = inner[3*j+2];
            float w  = fmaf(gx, gx, fmaf(gy, gy, gz * gz));
            float t  = fmaf(-2.0f * gx, cx, w);
            t = fmaf(-2.0f * gy, cy, t);
            t = fmaf(-2.0f * gz, cz, t);
            cm = fminf(cm, t);
        }
#pragma unroll
        for (int off = 16; off; off >>= 1)
            cm = fminf(cm, __shfl_xor_sync(0xffffffffu, cm, off));
        if (lane == 0) s_red[tid >> 5] = cm;
    }
    __syncthreads();
    if (tid == 0) {
        float m = s_red[0];
#pragma unroll
        for (int w = 1; w < T / 32; w++) m = fminf(m, s_red[w]);
        float lb = m + s_cand.w;                      // exact min-d^2, valid LB
        s_lb = lb - fabsf(lb) * 1e-5f - 1e-12f;
        g_lb4[dir][b][och] = s_lb;
    }

    // ---- branchless phase-1 scan (64 slots = 128 pts) ----
    u64t px2[OPT], py2[OPT], pz2[OPT];
    float mn[OPT];
#pragma unroll
    for (int o = 0; o < OPT; o++) {
        px2[o] = pk(px[o], px[o]);
        py2[o] = pk(py[o], py[o]);
        pz2[o] = pk(pz[o], pz[o]);
        mn[o]  = FLT_MAX;
    }
#pragma unroll 8
    for (int s = 0; s < P1SLOTS; s++) {
        ulonglong2 ab = shv[s * 2 + 0];
        ulonglong2 cd = shv[s * 2 + 1];
#pragma unroll
        for (int o = 0; o < OPT; o++) {
            u64t t = fma2(ab.x, px2[o], cd.y);
            t = fma2(ab.y, py2[o], t);
            t = fma2(cd.x, pz2[o], t);
            float2 tv = upk(t);
            mn[o] = fminf(mn[o], fminf(tv.x, tv.y));
        }
    }
    __syncthreads();                                  // s_lb visible

    // ---- filter: certified -> block max; uncertified -> global list ----
    {
        const float lbm = s_lb;
        float cmax = -FLT_MAX;
#pragma unroll
        for (int o = 0; o < OPT; o++) {
            int gi = gbase + o * T + tid;
            float v = mn[o] + rq[o];
            if (v < lbm) {
                cmax = fmaxf(cmax, v);
            } else {
                int k = atomicAdd(&g_cnt, 1);
                g_list[k] = make_int2((dir << 16) | (b << 12) | gi,
                                      __float_as_int(v));
            }
        }
#pragma unroll
        for (int off = 16; off; off >>= 1)
            cmax = fmaxf(cmax, __shfl_xor_sync(0xffffffffu, cmax, off));
        if (lane == 0) s_red[tid >> 5] = cmax;
        __syncthreads();
        if (tid == 0) {
            float m = s_red[0];
#pragma unroll
            for (int w = 1; w < T / 32; w++) m = fmaxf(m, s_red[w]);
            g_bmax4[dir][b][och] = encf(m);           // plain store, own slot
        }
    }
    gbar();

    // ================= Phase C: work-stealing warp-per-point tail ===========
    {
        const int cnt = g_cnt;
        int u;
        if (lane == 0) u = atomicAdd(&g_ticket, 1);
        u = __shfl_sync(0xffffffffu, u, 0);
        while (u < cnt) {
            const int2 e = g_list[u];
            const int code = e.x;
            const float partial = __int_as_float(e.y);
            const int gi = code & 4095, bb = (code >> 12) & 15, dd = code >> 16;
            const float* __restrict__ po = (dd == 0 ? preds : gts) + (size_t)bb * NPTS * 3;

            const float x = po[3*gi], y = po[3*gi+1], z = po[3*gi+2];
            const float rqp = fmaf(x, x, fmaf(y, y, z*z));
            float lbm = fmaxf(fmaxf(g_lb4[dd][bb][0], g_lb4[dd][bb][1]),
                              fmaxf(g_lb4[dd][bb][2], g_lb4[dd][bb][3]));
            const float thr = lbm - rqp;              // s-domain threshold
            const float4* packp = &g_pack[dd ^ 1][bb][0];

            float m = FLT_MAX;
            // half round: inner points [P1PTS, TAIL0) = 128 pts (4 lane-iters)
#pragma unroll
            for (int k = 0; k < (TAIL0 - P1PTS) / 32; k++) {
                float4 p = packp[P1PTS + k * 32 + lane];
                float t = fmaf(p.x, x, p.w);
                t = fmaf(p.y, y, t);
                t = fmaf(p.z, z, t);
                m = fminf(m, t);
            }
            if (!__any_sync(0xffffffffu, m < thr)) {
                // full rounds: [TAIL0, NPTS) = 3840 pts = 15 rounds of 256
                for (int base = TAIL0; base < NPTS; base += 32 * VC) {
#pragma unroll
                    for (int k = 0; k < VC; k++) {
                        float4 p = packp[base + k * 32 + lane];
                        float t = fmaf(p.x, x, p.w);
                        t = fmaf(p.y, y, t);
                        t = fmaf(p.z, z, t);
                        m = fminf(m, t);
                    }
                    if (__any_sync(0xffffffffu, m < thr)) break;   // certified
                }
            }
#pragma unroll
            for (int off = 16; off; off >>= 1)
                m = fminf(m, __shfl_xor_sync(0xffffffffu, m, off));
            if (lane == 0)
                atomicMax(&g_bmax4[dd][bb][gi >> 10],
                          encf(fminf(partial, m + rqp)));

            if (lane == 0) u = atomicAdd(&g_ticket, 1);
            u = __shfl_sync(0xffffffffu, u, 0);
        }
    }

    // ============ done-ticket final: last block writes out + resets =========
    __threadfence();
    __syncthreads();
    if (tid == 0) {
        s_last = (atomicAdd(&g_done, 1u) == NBLK - 1);
    }
    __syncthreads();
    if (s_last) {
        if (tid < BATCH) {
            unsigned int a = ldacq(&g_bmax4[0][tid][0]);
            unsigned int c = ldacq(&g_bmax4[1][tid][0]);
#pragma unroll
            for (int o = 1; o < OCH; o++) {
                unsigned int a2 = ldacq(&g_bmax4[0][tid][o]);
                unsigned int c2 = ldacq(&g_bmax4[1][tid][o]);
                a = (a2 > a) ? a2 : a;
                c = (c2 > c) ? c2 : c;
            }
            out[tid] = 0.5f * (decf(a) + decf(c));
        }
        if (tid == 32) {                               // reset for next launch
            g_cnt = 0; g_ticket = 0; g_done = 0u;
        }
    }
}

extern "C" void kernel_launch(void* const* d_in, const int* in_sizes, int n_in,
                              void* d_out, int out_size) {
    const float* preds = (const float*)d_in[0];
    const float* gts   = (const float*)d_in[1];
    float* out = (float*)d_out;

    hd_fused<<<NBLK, T>>>(preds, gts, out);
}